// round 8
// baseline (speedup 1.0000x reference)
#include <cuda_runtime.h>
#include <math.h>
#include <stdint.h>

#define M_MEM  50
#define D_DIM  64
#define PAD    68   // row stride in floats; float4-aligned, conflict-free phases
#define HALVES 4    // batch rows per block

struct SmemLayout {
    unsigned long long ctbS2[HALVES][8];    // packed f32x2 ctb (16 floats/half)
    float memS[HALVES][M_MEM * PAD];
    float w1S[128 * 16];                    // full att_w1
    float predW[192 * 8];
    float itemS[HALVES][D_DIM];
    float groupS[HALVES][D_DIM];
    float gS[HALVES][D_DIM];
    float w2S[16];
    float cS[20];   // [0]=att_b2, [1..8]=pred_b1, [9..16]=pred_w2, [17]=pred_b2
    float spS[HALVES][2][M_MEM];
    float wtS[HALVES][M_MEM];
};

// per-half barrier: 2 warps (64 threads) of this half only
#define HBAR() asm volatile("bar.sync %0, %1;" :: "r"(half + 1), "r"(64) : "memory")

__global__ __launch_bounds__(256, 3)
void agree_fused_kernel(
    const int* __restrict__ group_inputs,
    const int* __restrict__ item_inputs,
    const int* __restrict__ member_ids,
    const int* __restrict__ member_lengths,
    const float* __restrict__ user_table,
    const float* __restrict__ item_table,
    const float* __restrict__ group_table,
    const float* __restrict__ att_w1,   // [128,16]
    const float* __restrict__ att_b1,   // [16]
    const float* __restrict__ att_w2,   // [16]
    const float* __restrict__ att_b2,   // [1]
    const float* __restrict__ pred_w1,  // [192,8]
    const float* __restrict__ pred_b1,  // [8]
    const float* __restrict__ pred_w2,  // [8]
    const float* __restrict__ pred_b2,  // [1]
    float* __restrict__ out,            // [B]
    int Btot)
{
    extern __shared__ char smemRaw[];
    SmemLayout& S = *reinterpret_cast<SmemLayout*>(smemRaw);

    const int tid  = threadIdx.x;
    const int half = tid >> 6;          // 0..3
    const int lt   = tid & 63;
    const int wih  = (lt >> 5);         // warp-in-half: owns j-octet
    const int l    = lt & 31;           // lane
    const int b    = blockIdx.x * HALVES + half;
    const bool valid = (b < Btot);
    const int bc   = valid ? b : 0;

    const int item_idx = item_inputs[bc];
    const int grp_idx  = group_inputs[bc];
    const int len      = member_lengths[bc];

    // ---- per-thread member-id prefetch (registers; no staging barrier) ----
    int ids[13];
    #pragma unroll
    for (int k = 0; k < 13; k++) {
        int i = lt + 64 * k;
        if (i < M_MEM * 16) ids[k] = member_ids[bc * M_MEM + (i >> 4)];
    }

    // ---- async gather of 50 member rows into smem (16B cp.async each) ----
    #pragma unroll
    for (int k = 0; k < 13; k++) {
        int i = lt + 64 * k;
        if (i < M_MEM * 16) {
            int r = i >> 4, c = i & 15;
            const float* src = user_table + (size_t)ids[k] * D_DIM + c * 4;
            uint32_t dst = (uint32_t)__cvta_generic_to_shared(S.memS[half] + r * PAD + c * 4);
            asm volatile("cp.async.cg.shared.global [%0], [%1], 16;" :: "r"(dst), "l"(src));
        }
    }
    asm volatile("cp.async.commit_group;");

    S.itemS[half][lt]  = item_table[item_idx * D_DIM + lt];
    S.groupS[half][lt] = group_table[grp_idx * D_DIM + lt];

    // stage full att_w1 (512 float4) and pred_w1 (384 float4); 256 threads
    {
        float4* dstA = (float4*)S.w1S;
        const float4* srcA = (const float4*)att_w1;
        dstA[tid]       = srcA[tid];
        dstA[tid + 256] = srcA[tid + 256];
        if (tid < 128) {
            float4* dstP = (float4*)S.predW;
            const float4* srcP = (const float4*)pred_w1;
            #pragma unroll
            for (int i = 0; i < 3; i++) dstP[tid + i * 128] = srcP[tid + i * 128];
        }
    }
    if (tid < 16) S.w2S[tid] = att_w2[tid];
    if (tid == 16) { S.cS[0] = att_b2[0]; S.cS[17] = pred_b2[0]; }
    if (tid >= 32 && tid < 40) {
        S.cS[1 + tid - 32] = pred_b1[tid - 32];
        S.cS[9 + tid - 32] = pred_w2[tid - 32];
    }
    __syncthreads();   // weights + itemS visible block-wide (ONLY block-wide sync)

    // ctb[j] = b1[j] + sum_d item[d]*W1[64+d][j]  (16 threads/half, from smem)
    if (lt < 16) {
        float a = att_b1[lt];
        #pragma unroll 8
        for (int d = 0; d < D_DIM; d++)
            a += S.itemS[half][d] * S.w1S[(D_DIM + d) * 16 + lt];
        ((float*)S.ctbS2[half])[lt] = a;
    }
    // member tiles: wait own cp.asyncs, then half-barrier makes all visible
    asm volatile("cp.async.wait_group 0;");
    HBAR();   // memS + ctb ready for this half

    // ---- attention scores ----
    // warp wih handles j-octet [8*wih, 8*wih+8); each lane handles members l and l+25
    if (l < 25) {
        const int m0 = l, m1 = l + 25;
        unsigned long long accA[4], accB[4];
        #pragma unroll
        for (int i = 0; i < 4; i++) {
            unsigned long long c0 = S.ctbS2[half][wih * 4 + i];
            accA[i] = c0; accB[i] = c0;
        }
        const float4* mrow0 = (const float4*)(S.memS[half] + m0 * PAD);
        const float4* mrow1 = (const float4*)(S.memS[half] + m1 * PAD);
        const uint32_t wbase = (uint32_t)__cvta_generic_to_shared(S.w1S) + wih * 32;

        #pragma unroll 4
        for (int dq = 0; dq < 16; dq++) {
            float4 a0 = mrow0[dq];
            float4 a1 = mrow1[dq];
            #pragma unroll
            for (int r = 0; r < 4; r++) {
                float v0 = (r == 0) ? a0.x : (r == 1) ? a0.y : (r == 2) ? a0.z : a0.w;
                float v1 = (r == 0) ? a1.x : (r == 1) ? a1.y : (r == 2) ? a1.z : a1.w;
                unsigned long long mm0, mm1;
                uint32_t u0 = __float_as_uint(v0), u1 = __float_as_uint(v1);
                asm("mov.b64 %0, {%1, %1};" : "=l"(mm0) : "r"(u0));
                asm("mov.b64 %0, {%1, %1};" : "=l"(mm1) : "r"(u1));
                uint32_t wa = wbase + (dq * 4 + r) * 64;    // 16 floats (64B) per d row
                unsigned long long w0, w1, w2, w3;
                asm("ld.shared.v2.u64 {%0,%1}, [%2];"   : "=l"(w0), "=l"(w1) : "r"(wa));
                asm("ld.shared.v2.u64 {%0,%1}, [%2+16];": "=l"(w2), "=l"(w3) : "r"(wa));
                asm("fma.rn.f32x2 %0, %1, %2, %0;" : "+l"(accA[0]) : "l"(mm0), "l"(w0));
                asm("fma.rn.f32x2 %0, %1, %2, %0;" : "+l"(accA[1]) : "l"(mm0), "l"(w1));
                asm("fma.rn.f32x2 %0, %1, %2, %0;" : "+l"(accA[2]) : "l"(mm0), "l"(w2));
                asm("fma.rn.f32x2 %0, %1, %2, %0;" : "+l"(accA[3]) : "l"(mm0), "l"(w3));
                asm("fma.rn.f32x2 %0, %1, %2, %0;" : "+l"(accB[0]) : "l"(mm1), "l"(w0));
                asm("fma.rn.f32x2 %0, %1, %2, %0;" : "+l"(accB[1]) : "l"(mm1), "l"(w1));
                asm("fma.rn.f32x2 %0, %1, %2, %0;" : "+l"(accB[2]) : "l"(mm1), "l"(w2));
                asm("fma.rn.f32x2 %0, %1, %2, %0;" : "+l"(accB[3]) : "l"(mm1), "l"(w3));
            }
        }
        float s0 = 0.0f, s1 = 0.0f;
        #pragma unroll
        for (int i = 0; i < 4; i++) {
            uint32_t alo, ahi, blo, bhi;
            asm("mov.b64 {%0,%1}, %2;" : "=r"(alo), "=r"(ahi) : "l"(accA[i]));
            asm("mov.b64 {%0,%1}, %2;" : "=r"(blo), "=r"(bhi) : "l"(accB[i]));
            float w2lo = S.w2S[wih * 8 + 2 * i], w2hi = S.w2S[wih * 8 + 2 * i + 1];
            s0 += fmaxf(__uint_as_float(alo), 0.0f) * w2lo
                + fmaxf(__uint_as_float(ahi), 0.0f) * w2hi;
            s1 += fmaxf(__uint_as_float(blo), 0.0f) * w2lo
                + fmaxf(__uint_as_float(bhi), 0.0f) * w2hi;
        }
        S.spS[half][wih][m0] = s0;
        S.spS[half][wih][m1] = s1;
    }
    HBAR();

    // ---- softmax over 50 scores (warp 0 of each half) ----
    if (lt < 32) {
        float bias2 = S.cS[0];
        float v1 = S.spS[half][0][lt] + S.spS[half][1][lt] + bias2;
        v1 = (lt <= len) ? v1 : -INFINITY;
        float v2 = -INFINITY;
        if (lt + 32 < M_MEM) {
            v2 = S.spS[half][0][lt + 32] + S.spS[half][1][lt + 32] + bias2;
            v2 = (lt + 32 <= len) ? v2 : -INFINITY;
        }
        float mx = fmaxf(v1, v2);
        #pragma unroll
        for (int o = 16; o > 0; o >>= 1)
            mx = fmaxf(mx, __shfl_xor_sync(0xffffffffu, mx, o));
        float e1 = __expf(v1 - mx);
        float e2 = (lt + 32 < M_MEM) ? __expf(v2 - mx) : 0.0f;
        float sm = e1 + e2;
        #pragma unroll
        for (int o = 16; o > 0; o >>= 1)
            sm += __shfl_xor_sync(0xffffffffu, sm, o);
        float inv = __frcp_rn(sm);
        S.wtS[half][lt] = e1 * inv;
        if (lt + 32 < M_MEM) S.wtS[half][lt + 32] = e2 * inv;
    }
    HBAR();

    // ---- weighted member sum + group: 32 lanes/half, f32x2 over dim pairs ----
    if (lt < 32) {
        unsigned long long g2 = *((const unsigned long long*)(S.groupS[half] + 2 * lt));
        const char* mbase = (const char*)(S.memS[half]) + lt * 8;
        #pragma unroll 10
        for (int m = 0; m < M_MEM; m++) {
            unsigned long long mv = *((const unsigned long long*)(mbase + m * (PAD * 4)));
            float wt = S.wtS[half][m];
            unsigned long long wt2;
            uint32_t wtu = __float_as_uint(wt);
            asm("mov.b64 %0, {%1, %1};" : "=l"(wt2) : "r"(wtu));
            asm("fma.rn.f32x2 %0, %1, %2, %0;" : "+l"(g2) : "l"(wt2), "l"(mv));
        }
        *((unsigned long long*)(S.gS[half] + 2 * lt)) = g2;
    }
    HBAR();

    // ---- predict MLP: new_e = [g*item, g, item] (192) -> 8 -> 1, 32 lanes/half ----
    // lane = c*8 + j ; k = c + 4*kk (stride-4 so the 4 c-groups hit one 128B line)
    if (lt < 32) {
        const int j = lt & 7;           // hidden unit
        const int c = lt >> 3;          // k-phase 0..3
        float a = (c == 0) ? S.cS[1 + j] : 0.0f;
        #pragma unroll 8
        for (int kk = 0; kk < 48; kk++) {
            int k = c + 4 * kk;
            float v = (k < 64) ? S.gS[half][k] * S.itemS[half][k]
                   : (k < 128) ? S.gS[half][k - 64]
                               : S.itemS[half][k - 128];
            a += v * S.predW[k * 8 + j];
        }
        a += __shfl_xor_sync(0xffffffffu, a, 8);
        a += __shfl_xor_sync(0xffffffffu, a, 16);
        float part = fmaxf(a, 0.0f) * S.cS[9 + j];
        part += __shfl_xor_sync(0xffffffffu, part, 1);
        part += __shfl_xor_sync(0xffffffffu, part, 2);
        part += __shfl_xor_sync(0xffffffffu, part, 4);
        if (lt == 0 && valid) {
            float z = part + S.cS[17];
            out[b] = 1.0f / (1.0f + __expf(-z));
        }
    }
}

extern "C" void kernel_launch(void* const* d_in, const int* in_sizes, int n_in,
                              void* d_out, int out_size)
{
    const int*   group_inputs   = (const int*)  d_in[0];
    const int*   item_inputs    = (const int*)  d_in[1];
    const int*   member_ids     = (const int*)  d_in[2];
    const int*   member_lengths = (const int*)  d_in[3];
    const float* user_table     = (const float*)d_in[4];
    const float* item_table     = (const float*)d_in[5];
    const float* group_table    = (const float*)d_in[6];
    const float* att_w1         = (const float*)d_in[7];
    const float* att_b1         = (const float*)d_in[8];
    const float* att_w2         = (const float*)d_in[9];
    const float* att_b2         = (const float*)d_in[10];
    const float* pred_w1        = (const float*)d_in[11];
    const float* pred_b1        = (const float*)d_in[12];
    const float* pred_w2        = (const float*)d_in[13];
    const float* pred_b2        = (const float*)d_in[14];
    float* out = (float*)d_out;

    int B = in_sizes[0];
    int smemBytes = (int)sizeof(SmemLayout);
    cudaFuncSetAttribute(agree_fused_kernel,
                         cudaFuncAttributeMaxDynamicSharedMemorySize, smemBytes);
    int grid = (B + HALVES - 1) / HALVES;
    agree_fused_kernel<<<grid, 256, smemBytes>>>(
        group_inputs, item_inputs, member_ids, member_lengths,
        user_table, item_table, group_table,
        att_w1, att_b1, att_w2, att_b2,
        pred_w1, pred_b1, pred_w2, pred_b2, out, B);
}

// round 11
// speedup vs baseline: 1.5049x; 1.5049x over previous
#include <cuda_runtime.h>
#include <math.h>
#include <stdint.h>

#define M_MEM  50
#define D_DIM  64
#define PAD    68   // row stride in floats; float4-aligned, conflict-free phases
#define HALVES 4    // batch rows per block

struct SmemLayout {
    unsigned long long ctbS2[HALVES][8];    // packed f32x2 ctb (16 floats/half)
    float memS[HALVES][M_MEM * PAD];
    float w1S[128 * 16];                    // full att_w1
    float predW[192 * 8];
    float itemS[HALVES][D_DIM];
    float groupS[HALVES][D_DIM];
    float gS[HALVES][D_DIM];
    float w2S[16];
    float cS[20];   // [0]=att_b2, [1..8]=pred_b1, [9..16]=pred_w2, [17]=pred_b2
    float spS[HALVES][2][M_MEM];
    float wtS[HALVES][M_MEM];
};

// per-half barrier: 2 warps (64 threads) of this half only
#define HBAR() asm volatile("bar.sync %0, %1;" :: "r"(half + 1), "r"(64) : "memory")

__global__ __launch_bounds__(256, 3)
void agree_fused_kernel(
    const int* __restrict__ group_inputs,
    const int* __restrict__ item_inputs,
    const int* __restrict__ member_ids,
    const int* __restrict__ member_lengths,
    const float* __restrict__ user_table,
    const float* __restrict__ item_table,
    const float* __restrict__ group_table,
    const float* __restrict__ att_w1,   // [128,16]
    const float* __restrict__ att_b1,   // [16]
    const float* __restrict__ att_w2,   // [16]
    const float* __restrict__ att_b2,   // [1]
    const float* __restrict__ pred_w1,  // [192,8]
    const float* __restrict__ pred_b1,  // [8]
    const float* __restrict__ pred_w2,  // [8]
    const float* __restrict__ pred_b2,  // [1]
    float* __restrict__ out,            // [B]
    int Btot)
{
    extern __shared__ char smemRaw[];
    SmemLayout& S = *reinterpret_cast<SmemLayout*>(smemRaw);

    const int tid  = threadIdx.x;
    const int half = tid >> 6;          // 0..3
    const int lt   = tid & 63;
    const int wih  = (lt >> 5);         // warp-in-half: owns j-octet
    const int l    = lt & 31;           // lane
    const int b    = blockIdx.x * HALVES + half;
    const bool valid = (b < Btot);
    const int bc   = valid ? b : 0;

    const int item_idx = item_inputs[bc];
    const int grp_idx  = group_inputs[bc];
    const int len      = member_lengths[bc];

    // ---- per-thread member-id prefetch (registers; no staging barrier) ----
    int ids[13];
    #pragma unroll
    for (int k = 0; k < 13; k++) {
        int i = lt + 64 * k;
        if (i < M_MEM * 16) ids[k] = member_ids[bc * M_MEM + (i >> 4)];
    }

    // ---- gather 50 member rows into smem (16 float4/row), issued ASAP ----
    #pragma unroll
    for (int k = 0; k < 13; k++) {
        int i = lt + 64 * k;
        if (i < M_MEM * 16) {
            int r = i >> 4, c = i & 15;
            float4 v = ((const float4*)(user_table + (size_t)ids[k] * D_DIM))[c];
            *((float4*)(S.memS[half] + r * PAD + c * 4)) = v;
        }
    }

    S.itemS[half][lt]  = item_table[item_idx * D_DIM + lt];
    S.groupS[half][lt] = group_table[grp_idx * D_DIM + lt];

    // stage full att_w1 (512 float4) and pred_w1 (384 float4); 256 threads
    {
        float4* dstA = (float4*)S.w1S;
        const float4* srcA = (const float4*)att_w1;
        dstA[tid]       = srcA[tid];
        dstA[tid + 256] = srcA[tid + 256];
        if (tid < 128) {
            float4* dstP = (float4*)S.predW;
            const float4* srcP = (const float4*)pred_w1;
            #pragma unroll
            for (int i = 0; i < 3; i++) dstP[tid + i * 128] = srcP[tid + i * 128];
        }
    }
    if (tid < 16) S.w2S[tid] = att_w2[tid];
    if (tid == 16) { S.cS[0] = att_b2[0]; S.cS[17] = pred_b2[0]; }
    if (tid >= 32 && tid < 40) {
        S.cS[1 + tid - 32] = pred_b1[tid - 32];
        S.cS[9 + tid - 32] = pred_w2[tid - 32];
    }
    __syncthreads();   // memS + itemS + weights visible (ONLY block-wide sync)

    // ctb[j] = b1[j] + sum_d item[d]*W1[64+d][j]  (16 threads/half, from smem)
    if (lt < 16) {
        float a = att_b1[lt];
        #pragma unroll 8
        for (int d = 0; d < D_DIM; d++)
            a += S.itemS[half][d] * S.w1S[(D_DIM + d) * 16 + lt];
        ((float*)S.ctbS2[half])[lt] = a;
    }
    HBAR();   // ctb ready for this half; from here halves free-run

    // ---- attention scores ----
    // warp wih handles j-octet [8*wih, 8*wih+8); each lane handles members l and l+25
    if (l < 25) {
        const int m0 = l, m1 = l + 25;
        unsigned long long accA[4], accB[4];
        #pragma unroll
        for (int i = 0; i < 4; i++) {
            unsigned long long c0 = S.ctbS2[half][wih * 4 + i];
            accA[i] = c0; accB[i] = c0;
        }
        const float4* mrow0 = (const float4*)(S.memS[half] + m0 * PAD);
        const float4* mrow1 = (const float4*)(S.memS[half] + m1 * PAD);
        const uint32_t wbase = (uint32_t)__cvta_generic_to_shared(S.w1S) + wih * 32;

        #pragma unroll 4
        for (int dq = 0; dq < 16; dq++) {
            float4 a0 = mrow0[dq];
            float4 a1 = mrow1[dq];
            #pragma unroll
            for (int r = 0; r < 4; r++) {
                float v0 = (r == 0) ? a0.x : (r == 1) ? a0.y : (r == 2) ? a0.z : a0.w;
                float v1 = (r == 0) ? a1.x : (r == 1) ? a1.y : (r == 2) ? a1.z : a1.w;
                unsigned long long mm0, mm1;
                uint32_t u0 = __float_as_uint(v0), u1 = __float_as_uint(v1);
                asm("mov.b64 %0, {%1, %1};" : "=l"(mm0) : "r"(u0));
                asm("mov.b64 %0, {%1, %1};" : "=l"(mm1) : "r"(u1));
                uint32_t wa = wbase + (dq * 4 + r) * 64;    // 16 floats (64B) per d row
                unsigned long long w0, w1, w2, w3;
                asm("ld.shared.v2.u64 {%0,%1}, [%2];"   : "=l"(w0), "=l"(w1) : "r"(wa));
                asm("ld.shared.v2.u64 {%0,%1}, [%2+16];": "=l"(w2), "=l"(w3) : "r"(wa));
                asm("fma.rn.f32x2 %0, %1, %2, %0;" : "+l"(accA[0]) : "l"(mm0), "l"(w0));
                asm("fma.rn.f32x2 %0, %1, %2, %0;" : "+l"(accA[1]) : "l"(mm0), "l"(w1));
                asm("fma.rn.f32x2 %0, %1, %2, %0;" : "+l"(accA[2]) : "l"(mm0), "l"(w2));
                asm("fma.rn.f32x2 %0, %1, %2, %0;" : "+l"(accA[3]) : "l"(mm0), "l"(w3));
                asm("fma.rn.f32x2 %0, %1, %2, %0;" : "+l"(accB[0]) : "l"(mm1), "l"(w0));
                asm("fma.rn.f32x2 %0, %1, %2, %0;" : "+l"(accB[1]) : "l"(mm1), "l"(w1));
                asm("fma.rn.f32x2 %0, %1, %2, %0;" : "+l"(accB[2]) : "l"(mm1), "l"(w2));
                asm("fma.rn.f32x2 %0, %1, %2, %0;" : "+l"(accB[3]) : "l"(mm1), "l"(w3));
            }
        }
        float s0 = 0.0f, s1 = 0.0f;
        #pragma unroll
        for (int i = 0; i < 4; i++) {
            uint32_t alo, ahi, blo, bhi;
            asm("mov.b64 {%0,%1}, %2;" : "=r"(alo), "=r"(ahi) : "l"(accA[i]));
            asm("mov.b64 {%0,%1}, %2;" : "=r"(blo), "=r"(bhi) : "l"(accB[i]));
            float w2lo = S.w2S[wih * 8 + 2 * i], w2hi = S.w2S[wih * 8 + 2 * i + 1];
            s0 += fmaxf(__uint_as_float(alo), 0.0f) * w2lo
                + fmaxf(__uint_as_float(ahi), 0.0f) * w2hi;
            s1 += fmaxf(__uint_as_float(blo), 0.0f) * w2lo
                + fmaxf(__uint_as_float(bhi), 0.0f) * w2hi;
        }
        S.spS[half][wih][m0] = s0;
        S.spS[half][wih][m1] = s1;
    }
    HBAR();

    // ---- softmax over 50 scores (warp 0 of each half) ----
    if (lt < 32) {
        float bias2 = S.cS[0];
        float v1 = S.spS[half][0][lt] + S.spS[half][1][lt] + bias2;
        v1 = (lt <= len) ? v1 : -INFINITY;
        float v2 = -INFINITY;
        if (lt + 32 < M_MEM) {
            v2 = S.spS[half][0][lt + 32] + S.spS[half][1][lt + 32] + bias2;
            v2 = (lt + 32 <= len) ? v2 : -INFINITY;
        }
        float mx = fmaxf(v1, v2);
        #pragma unroll
        for (int o = 16; o > 0; o >>= 1)
            mx = fmaxf(mx, __shfl_xor_sync(0xffffffffu, mx, o));
        float e1 = __expf(v1 - mx);
        float e2 = (lt + 32 < M_MEM) ? __expf(v2 - mx) : 0.0f;
        float sm = e1 + e2;
        #pragma unroll
        for (int o = 16; o > 0; o >>= 1)
            sm += __shfl_xor_sync(0xffffffffu, sm, o);
        float inv = __frcp_rn(sm);
        S.wtS[half][lt] = e1 * inv;
        if (lt + 32 < M_MEM) S.wtS[half][lt + 32] = e2 * inv;
    }
    HBAR();

    // ---- weighted member sum + group: 32 lanes/half, f32x2 over dim pairs ----
    if (lt < 32) {
        unsigned long long g2 = *((const unsigned long long*)(S.groupS[half] + 2 * lt));
        const char* mbase = (const char*)(S.memS[half]) + lt * 8;
        #pragma unroll 10
        for (int m = 0; m < M_MEM; m++) {
            unsigned long long mv = *((const unsigned long long*)(mbase + m * (PAD * 4)));
            float wt = S.wtS[half][m];
            unsigned long long wt2;
            uint32_t wtu = __float_as_uint(wt);
            asm("mov.b64 %0, {%1, %1};" : "=l"(wt2) : "r"(wtu));
            asm("fma.rn.f32x2 %0, %1, %2, %0;" : "+l"(g2) : "l"(wt2), "l"(mv));
        }
        *((unsigned long long*)(S.gS[half] + 2 * lt)) = g2;
    }
    HBAR();

    // ---- predict MLP: new_e = [g*item, g, item] (192) -> 8 -> 1, 32 lanes/half ----
    // lane = c*8 + j ; k = c + 4*kk (stride-4 so the 4 c-groups hit one 128B line)
    if (lt < 32) {
        const int j = lt & 7;           // hidden unit
        const int c = lt >> 3;          // k-phase 0..3
        float a = (c == 0) ? S.cS[1 + j] : 0.0f;
        #pragma unroll 8
        for (int kk = 0; kk < 48; kk++) {
            int k = c + 4 * kk;
            float v = (k < 64) ? S.gS[half][k] * S.itemS[half][k]
                   : (k < 128) ? S.gS[half][k - 64]
                               : S.itemS[half][k - 128];
            a += v * S.predW[k * 8 + j];
        }
        a += __shfl_xor_sync(0xffffffffu, a, 8);
        a += __shfl_xor_sync(0xffffffffu, a, 16);
        float part = fmaxf(a, 0.0f) * S.cS[9 + j];
        part += __shfl_xor_sync(0xffffffffu, part, 1);
        part += __shfl_xor_sync(0xffffffffu, part, 2);
        part += __shfl_xor_sync(0xffffffffu, part, 4);
        if (lt == 0 && valid) {
            float z = part + S.cS[17];
            out[b] = 1.0f / (1.0f + __expf(-z));
        }
    }
}

extern "C" void kernel_launch(void* const* d_in, const int* in_sizes, int n_in,
                              void* d_out, int out_size)
{
    const int*   group_inputs   = (const int*)  d_in[0];
    const int*   item_inputs    = (const int*)  d_in[1];
    const int*   member_ids     = (const int*)  d_in[2];
    const int*   member_lengths = (const int*)  d_in[3];
    const float* user_table     = (const float*)d_in[4];
    const float* item_table     = (const float*)d_in[5];
    const float* group_table    = (const float*)d_in[6];
    const float* att_w1         = (const float*)d_in[7];
    const float* att_b1         = (const float*)d_in[8];
    const float* att_w2         = (const float*)d_in[9];
    const float* att_b2         = (const float*)d_in[10];
    const float* pred_w1        = (const float*)d_in[11];
    const float* pred_b1        = (const float*)d_in[12];
    const float* pred_w2        = (const float*)d_in[13];
    const float* pred_b2        = (const float*)d_in[14];
    float* out = (float*)d_out;

    int B = in_sizes[0];
    int smemBytes = (int)sizeof(SmemLayout);
    cudaFuncSetAttribute(agree_fused_kernel,
                         cudaFuncAttributeMaxDynamicSharedMemorySize, smemBytes);
    int grid = (B + HALVES - 1) / HALVES;
    agree_fused_kernel<<<grid, 256, smemBytes>>>(
        group_inputs, item_inputs, member_ids, member_lengths,
        user_table, item_table, group_table,
        att_w1, att_b1, att_w2, att_b2,
        pred_w1, pred_b1, pred_w2, pred_b2, out, B);
}

// round 14
// speedup vs baseline: 1.6216x; 1.0776x over previous
#include <cuda_runtime.h>
#include <math.h>
#include <stdint.h>

#define M_MEM  50
#define D_DIM  64
#define PAD    68   // row stride in floats; float4-aligned, conflict-free phases
#define HALVES 4    // batch rows per block

struct SmemLayout {
    unsigned long long ctbS2[HALVES][8];    // packed f32x2 ctb (16 floats/half)
    float memS[HALVES][M_MEM * PAD];
    float w1S[128 * 16];                    // full att_w1
    float predW[192 * 8];
    float itemS[HALVES][D_DIM];
    float groupS[HALVES][D_DIM];
    float gS[HALVES][D_DIM];
    float w2S[16];
    float cS[20];   // [0]=att_b2, [1..8]=pred_b1, [9..16]=pred_w2, [17]=pred_b2
    float spS[HALVES][2][M_MEM];            // partial scores; reused as pred scratch
    __align__(16) float wtS[HALVES][52];    // softmax weights (padded, 16B aligned)
};

// per-half barrier: 2 warps (64 threads) of this half only
#define HBAR() asm volatile("bar.sync %0, %1;" :: "r"(half + 1), "r"(64) : "memory")

__global__ __launch_bounds__(256, 3)
void agree_fused_kernel(
    const int* __restrict__ group_inputs,
    const int* __restrict__ item_inputs,
    const int* __restrict__ member_ids,
    const int* __restrict__ member_lengths,
    const float* __restrict__ user_table,
    const float* __restrict__ item_table,
    const float* __restrict__ group_table,
    const float* __restrict__ att_w1,   // [128,16]
    const float* __restrict__ att_b1,   // [16]
    const float* __restrict__ att_w2,   // [16]
    const float* __restrict__ att_b2,   // [1]
    const float* __restrict__ pred_w1,  // [192,8]
    const float* __restrict__ pred_b1,  // [8]
    const float* __restrict__ pred_w2,  // [8]
    const float* __restrict__ pred_b2,  // [1]
    float* __restrict__ out,            // [B]
    int Btot)
{
    extern __shared__ char smemRaw[];
    SmemLayout& S = *reinterpret_cast<SmemLayout*>(smemRaw);

    const int tid  = threadIdx.x;
    const int half = tid >> 6;          // 0..3
    const int lt   = tid & 63;
    const int wih  = (lt >> 5);         // warp-in-half
    const int l    = lt & 31;           // lane
    const int b    = blockIdx.x * HALVES + half;
    const bool valid = (b < Btot);
    const int bc   = valid ? b : 0;

    const int item_idx = item_inputs[bc];
    const int grp_idx  = group_inputs[bc];
    const int len      = member_lengths[bc];

    // ---- per-thread member-id prefetch (registers; no staging barrier) ----
    int ids[13];
    #pragma unroll
    for (int k = 0; k < 13; k++) {
        int i = lt + 64 * k;
        if (i < M_MEM * 16) ids[k] = member_ids[bc * M_MEM + (i >> 4)];
    }

    // ---- gather 50 member rows into smem (16 float4/row), issued ASAP ----
    #pragma unroll
    for (int k = 0; k < 13; k++) {
        int i = lt + 64 * k;
        if (i < M_MEM * 16) {
            int r = i >> 4, c = i & 15;
            float4 v = ((const float4*)(user_table + (size_t)ids[k] * D_DIM))[c];
            *((float4*)(S.memS[half] + r * PAD + c * 4)) = v;
        }
    }

    S.itemS[half][lt]  = item_table[item_idx * D_DIM + lt];
    S.groupS[half][lt] = group_table[grp_idx * D_DIM + lt];

    // stage full att_w1 (512 float4) and pred_w1 (384 float4); 256 threads
    {
        float4* dstA = (float4*)S.w1S;
        const float4* srcA = (const float4*)att_w1;
        dstA[tid]       = srcA[tid];
        dstA[tid + 256] = srcA[tid + 256];
        if (tid < 128) {
            float4* dstP = (float4*)S.predW;
            const float4* srcP = (const float4*)pred_w1;
            #pragma unroll
            for (int i = 0; i < 3; i++) dstP[tid + i * 128] = srcP[tid + i * 128];
        }
    }
    if (tid < 16) S.w2S[tid] = att_w2[tid];
    if (tid == 16) { S.cS[0] = att_b2[0]; S.cS[17] = pred_b2[0]; }
    if (tid >= 32 && tid < 40) {
        S.cS[1 + tid - 32] = pred_b1[tid - 32];
        S.cS[9 + tid - 32] = pred_w2[tid - 32];
    }
    __syncthreads();   // memS + itemS + weights visible (ONLY block-wide sync)

    // ---- ctb[j] = b1[j] + sum_d item[d]*W1[64+d][j] ----
    // warp0 of each half: 32 lanes = 16 j x 2 d-segments; shfl-combine (chain 64->32)
    if (wih == 0) {
        const int j = l & 15, seg = l >> 4;
        float a = 0.0f;
        #pragma unroll 8
        for (int dd = 0; dd < 32; dd++) {
            int d = seg * 32 + dd;
            a += S.itemS[half][d] * S.w1S[(D_DIM + d) * 16 + j];
        }
        a += __shfl_xor_sync(0xffffffffu, a, 16);
        if (l < 16) ((float*)S.ctbS2[half])[l] = att_b1[l] + a;
    }
    HBAR();   // ctb ready for this half; from here halves free-run

    // ---- attention scores ----
    // warp wih handles j-octet [8*wih, 8*wih+8); each lane handles members l and l+25
    if (l < 25) {
        const int m0 = l, m1 = l + 25;
        unsigned long long accA[4], accB[4];
        #pragma unroll
        for (int i = 0; i < 4; i++) {
            unsigned long long c0 = S.ctbS2[half][wih * 4 + i];
            accA[i] = c0; accB[i] = c0;
        }
        const float4* mrow0 = (const float4*)(S.memS[half] + m0 * PAD);
        const float4* mrow1 = (const float4*)(S.memS[half] + m1 * PAD);
        const uint32_t wbase = (uint32_t)__cvta_generic_to_shared(S.w1S) + wih * 32;

        #pragma unroll 4
        for (int dq = 0; dq < 16; dq++) {
            float4 a0 = mrow0[dq];
            float4 a1 = mrow1[dq];
            #pragma unroll
            for (int r = 0; r < 4; r++) {
                float v0 = (r == 0) ? a0.x : (r == 1) ? a0.y : (r == 2) ? a0.z : a0.w;
                float v1 = (r == 0) ? a1.x : (r == 1) ? a1.y : (r == 2) ? a1.z : a1.w;
                unsigned long long mm0, mm1;
                uint32_t u0 = __float_as_uint(v0), u1 = __float_as_uint(v1);
                asm("mov.b64 %0, {%1, %1};" : "=l"(mm0) : "r"(u0));
                asm("mov.b64 %0, {%1, %1};" : "=l"(mm1) : "r"(u1));
                uint32_t wa = wbase + (dq * 4 + r) * 64;    // 16 floats (64B) per d row
                unsigned long long w0, w1, w2, w3;
                asm("ld.shared.v2.u64 {%0,%1}, [%2];"   : "=l"(w0), "=l"(w1) : "r"(wa));
                asm("ld.shared.v2.u64 {%0,%1}, [%2+16];": "=l"(w2), "=l"(w3) : "r"(wa));
                asm("fma.rn.f32x2 %0, %1, %2, %0;" : "+l"(accA[0]) : "l"(mm0), "l"(w0));
                asm("fma.rn.f32x2 %0, %1, %2, %0;" : "+l"(accA[1]) : "l"(mm0), "l"(w1));
                asm("fma.rn.f32x2 %0, %1, %2, %0;" : "+l"(accA[2]) : "l"(mm0), "l"(w2));
                asm("fma.rn.f32x2 %0, %1, %2, %0;" : "+l"(accA[3]) : "l"(mm0), "l"(w3));
                asm("fma.rn.f32x2 %0, %1, %2, %0;" : "+l"(accB[0]) : "l"(mm1), "l"(w0));
                asm("fma.rn.f32x2 %0, %1, %2, %0;" : "+l"(accB[1]) : "l"(mm1), "l"(w1));
                asm("fma.rn.f32x2 %0, %1, %2, %0;" : "+l"(accB[2]) : "l"(mm1), "l"(w2));
                asm("fma.rn.f32x2 %0, %1, %2, %0;" : "+l"(accB[3]) : "l"(mm1), "l"(w3));
            }
        }
        float s0 = 0.0f, s1 = 0.0f;
        #pragma unroll
        for (int i = 0; i < 4; i++) {
            uint32_t alo, ahi, blo, bhi;
            asm("mov.b64 {%0,%1}, %2;" : "=r"(alo), "=r"(ahi) : "l"(accA[i]));
            asm("mov.b64 {%0,%1}, %2;" : "=r"(blo), "=r"(bhi) : "l"(accB[i]));
            float w2lo = S.w2S[wih * 8 + 2 * i], w2hi = S.w2S[wih * 8 + 2 * i + 1];
            s0 += fmaxf(__uint_as_float(alo), 0.0f) * w2lo
                + fmaxf(__uint_as_float(ahi), 0.0f) * w2hi;
            s1 += fmaxf(__uint_as_float(blo), 0.0f) * w2lo
                + fmaxf(__uint_as_float(bhi), 0.0f) * w2hi;
        }
        S.spS[half][wih][m0] = s0;
        S.spS[half][wih][m1] = s1;
    }
    HBAR();

    // ---- softmax over 50 scores (warp 0 of each half) ----
    if (lt < 32) {
        float bias2 = S.cS[0];
        float v1 = S.spS[half][0][lt] + S.spS[half][1][lt] + bias2;
        v1 = (lt <= len) ? v1 : -INFINITY;
        float v2 = -INFINITY;
        if (lt + 32 < M_MEM) {
            v2 = S.spS[half][0][lt + 32] + S.spS[half][1][lt + 32] + bias2;
            v2 = (lt + 32 <= len) ? v2 : -INFINITY;
        }
        float mx = fmaxf(v1, v2);
        #pragma unroll
        for (int o = 16; o > 0; o >>= 1)
            mx = fmaxf(mx, __shfl_xor_sync(0xffffffffu, mx, o));
        float e1 = __expf(v1 - mx);
        float e2 = (lt + 32 < M_MEM) ? __expf(v2 - mx) : 0.0f;
        float sm = e1 + e2;
        #pragma unroll
        for (int o = 16; o > 0; o >>= 1)
            sm += __shfl_xor_sync(0xffffffffu, sm, o);
        float inv = __frcp_rn(sm);
        S.wtS[half][lt] = e1 * inv;
        if (lt + 32 < M_MEM) S.wtS[half][lt + 32] = e2 * inv;
    }
    HBAR();

    // ---- weighted member sum + group: both warps (warp0 d0-31, warp1 d32-63) ----
    {
        const int d = wih * 32 + l;
        float g = S.groupS[half][d];
        const float* mcol = S.memS[half] + d;
        const float4* wt4 = (const float4*)S.wtS[half];
        #pragma unroll 4
        for (int q = 0; q < 12; q++) {
            float4 w = wt4[q];
            g += w.x * mcol[(4 * q + 0) * PAD];
            g += w.y * mcol[(4 * q + 1) * PAD];
            g += w.z * mcol[(4 * q + 2) * PAD];
            g += w.w * mcol[(4 * q + 3) * PAD];
        }
        g += S.wtS[half][48] * mcol[48 * PAD];
        g += S.wtS[half][49] * mcol[49 * PAD];
        S.gS[half][d] = g;
    }
    HBAR();

    // ---- predict MLP: new_e = [g*item, g, item] (192) -> 8 -> 1 ----
    // all 64 lanes: j = lt&7, c = lt>>3 (8 k-phases); k = c + 8*kk, 24 iters
    {
        const int j = lt & 7;
        const int c = lt >> 3;          // 0..7 across both warps
        float a = (c == 0) ? S.cS[1 + j] : 0.0f;
        #pragma unroll 8
        for (int kk = 0; kk < 24; kk++) {
            int k = c + 8 * kk;
            float v = (k < 64) ? S.gS[half][k] * S.itemS[half][k]
                   : (k < 128) ? S.gS[half][k - 64]
                               : S.itemS[half][k - 128];
            a += v * S.predW[k * 8 + j];
        }
        // intra-warp: sum this warp's 4 c-phases per j
        a += __shfl_xor_sync(0xffffffffu, a, 8);
        a += __shfl_xor_sync(0xffffffffu, a, 16);
        // cross-warp combine via spS scratch (dead after softmax)
        if (wih == 1 && l < 8) S.spS[half][0][l] = a;
    }
    HBAR();
    if (wih == 0 && l < 8) {
        float a;   // recompute handle: lane l holds j=l sum of warp0 phases
        // (a was consumed above; redo the tail on warp0's registers)
        // NOTE: warp0's reduced value lives in its lanes 0..7 from the block above.
        // We re-enter here in the same registers scope — recompute is avoided by
        // storing warp0's value too:
        a = 0.0f;   // placeholder, replaced below
        (void)a;
    }
    // final: warp0 lanes 0..7 combine with warp1 partial and finish
    {
        const int j = lt & 7;
        if (wih == 0 && l < 8) {
            // reload warp0 partial from the shfl result kept in spS[half][1]
            float aw0 = S.spS[half][1][j];
            float tot = aw0 + S.spS[half][0][j];
            float part = fmaxf(tot, 0.0f) * S.cS[9 + j];
            part += __shfl_xor_sync(0x000000ffu, part, 1);
            part += __shfl_xor_sync(0x000000ffu, part, 2);
            part += __shfl_xor_sync(0x000000ffu, part, 4);
            if (l == 0 && valid) {
                float z = part + S.cS[17];
                out[b] = 1.0f / (1.0f + __expf(-z));
            }
        }
    }
}

extern "C" void kernel_launch(void* const* d_in, const int* in_sizes, int n_in,
                              void* d_out, int out_size);

// --- corrected pred tail: warp0 must also publish its partial before HBAR ---
// (The kernel above references S.spS[half][1][j] for warp0's partial; the store
// is added here via a small fixup: we re-define the kernel body cleanly.)
// To keep a single translation unit and one kernel, the version that is
// actually launched is agree_fused_kernel2 below.

__global__ __launch_bounds__(256, 3)
void agree_fused_kernel2(
    const int* __restrict__ group_inputs,
    const int* __restrict__ item_inputs,
    const int* __restrict__ member_ids,
    const int* __restrict__ member_lengths,
    const float* __restrict__ user_table,
    const float* __restrict__ item_table,
    const float* __restrict__ group_table,
    const float* __restrict__ att_w1,
    const float* __restrict__ att_b1,
    const float* __restrict__ att_w2,
    const float* __restrict__ att_b2,
    const float* __restrict__ pred_w1,
    const float* __restrict__ pred_b1,
    const float* __restrict__ pred_w2,
    const float* __restrict__ pred_b2,
    float* __restrict__ out,
    int Btot)
{
    extern __shared__ char smemRaw[];
    SmemLayout& S = *reinterpret_cast<SmemLayout*>(smemRaw);

    const int tid  = threadIdx.x;
    const int half = tid >> 6;
    const int lt   = tid & 63;
    const int wih  = (lt >> 5);
    const int l    = lt & 31;
    const int b    = blockIdx.x * HALVES + half;
    const bool valid = (b < Btot);
    const int bc   = valid ? b : 0;

    const int item_idx = item_inputs[bc];
    const int grp_idx  = group_inputs[bc];
    const int len      = member_lengths[bc];

    int ids[13];
    #pragma unroll
    for (int k = 0; k < 13; k++) {
        int i = lt + 64 * k;
        if (i < M_MEM * 16) ids[k] = member_ids[bc * M_MEM + (i >> 4)];
    }
    #pragma unroll
    for (int k = 0; k < 13; k++) {
        int i = lt + 64 * k;
        if (i < M_MEM * 16) {
            int r = i >> 4, c = i & 15;
            float4 v = ((const float4*)(user_table + (size_t)ids[k] * D_DIM))[c];
            *((float4*)(S.memS[half] + r * PAD + c * 4)) = v;
        }
    }

    S.itemS[half][lt]  = item_table[item_idx * D_DIM + lt];
    S.groupS[half][lt] = group_table[grp_idx * D_DIM + lt];

    {
        float4* dstA = (float4*)S.w1S;
        const float4* srcA = (const float4*)att_w1;
        dstA[tid]       = srcA[tid];
        dstA[tid + 256] = srcA[tid + 256];
        if (tid < 128) {
            float4* dstP = (float4*)S.predW;
            const float4* srcP = (const float4*)pred_w1;
            #pragma unroll
            for (int i = 0; i < 3; i++) dstP[tid + i * 128] = srcP[tid + i * 128];
        }
    }
    if (tid < 16) S.w2S[tid] = att_w2[tid];
    if (tid == 16) { S.cS[0] = att_b2[0]; S.cS[17] = pred_b2[0]; }
    if (tid >= 32 && tid < 40) {
        S.cS[1 + tid - 32] = pred_b1[tid - 32];
        S.cS[9 + tid - 32] = pred_w2[tid - 32];
    }
    __syncthreads();

    // ctb: warp0, 32 lanes (16 j x 2 segments), shfl-combine
    if (wih == 0) {
        const int j = l & 15, seg = l >> 4;
        float a = 0.0f;
        #pragma unroll 8
        for (int dd = 0; dd < 32; dd++) {
            int d = seg * 32 + dd;
            a += S.itemS[half][d] * S.w1S[(D_DIM + d) * 16 + j];
        }
        a += __shfl_xor_sync(0xffffffffu, a, 16);
        if (l < 16) ((float*)S.ctbS2[half])[l] = att_b1[l] + a;
    }
    HBAR();

    // attention (unchanged proven mainloop)
    if (l < 25) {
        const int m0 = l, m1 = l + 25;
        unsigned long long accA[4], accB[4];
        #pragma unroll
        for (int i = 0; i < 4; i++) {
            unsigned long long c0 = S.ctbS2[half][wih * 4 + i];
            accA[i] = c0; accB[i] = c0;
        }
        const float4* mrow0 = (const float4*)(S.memS[half] + m0 * PAD);
        const float4* mrow1 = (const float4*)(S.memS[half] + m1 * PAD);
        const uint32_t wbase = (uint32_t)__cvta_generic_to_shared(S.w1S) + wih * 32;

        #pragma unroll 4
        for (int dq = 0; dq < 16; dq++) {
            float4 a0 = mrow0[dq];
            float4 a1 = mrow1[dq];
            #pragma unroll
            for (int r = 0; r < 4; r++) {
                float v0 = (r == 0) ? a0.x : (r == 1) ? a0.y : (r == 2) ? a0.z : a0.w;
                float v1 = (r == 0) ? a1.x : (r == 1) ? a1.y : (r == 2) ? a1.z : a1.w;
                unsigned long long mm0, mm1;
                uint32_t u0 = __float_as_uint(v0), u1 = __float_as_uint(v1);
                asm("mov.b64 %0, {%1, %1};" : "=l"(mm0) : "r"(u0));
                asm("mov.b64 %0, {%1, %1};" : "=l"(mm1) : "r"(u1));
                uint32_t wa = wbase + (dq * 4 + r) * 64;
                unsigned long long w0, w1, w2, w3;
                asm("ld.shared.v2.u64 {%0,%1}, [%2];"   : "=l"(w0), "=l"(w1) : "r"(wa));
                asm("ld.shared.v2.u64 {%0,%1}, [%2+16];": "=l"(w2), "=l"(w3) : "r"(wa));
                asm("fma.rn.f32x2 %0, %1, %2, %0;" : "+l"(accA[0]) : "l"(mm0), "l"(w0));
                asm("fma.rn.f32x2 %0, %1, %2, %0;" : "+l"(accA[1]) : "l"(mm0), "l"(w1));
                asm("fma.rn.f32x2 %0, %1, %2, %0;" : "+l"(accA[2]) : "l"(mm0), "l"(w2));
                asm("fma.rn.f32x2 %0, %1, %2, %0;" : "+l"(accA[3]) : "l"(mm0), "l"(w3));
                asm("fma.rn.f32x2 %0, %1, %2, %0;" : "+l"(accB[0]) : "l"(mm1), "l"(w0));
                asm("fma.rn.f32x2 %0, %1, %2, %0;" : "+l"(accB[1]) : "l"(mm1), "l"(w1));
                asm("fma.rn.f32x2 %0, %1, %2, %0;" : "+l"(accB[2]) : "l"(mm1), "l"(w2));
                asm("fma.rn.f32x2 %0, %1, %2, %0;" : "+l"(accB[3]) : "l"(mm1), "l"(w3));
            }
        }
        float s0 = 0.0f, s1 = 0.0f;
        #pragma unroll
        for (int i = 0; i < 4; i++) {
            uint32_t alo, ahi, blo, bhi;
            asm("mov.b64 {%0,%1}, %2;" : "=r"(alo), "=r"(ahi) : "l"(accA[i]));
            asm("mov.b64 {%0,%1}, %2;" : "=r"(blo), "=r"(bhi) : "l"(accB[i]));
            float w2lo = S.w2S[wih * 8 + 2 * i], w2hi = S.w2S[wih * 8 + 2 * i + 1];
            s0 += fmaxf(__uint_as_float(alo), 0.0f) * w2lo
                + fmaxf(__uint_as_float(ahi), 0.0f) * w2hi;
            s1 += fmaxf(__uint_as_float(blo), 0.0f) * w2lo
                + fmaxf(__uint_as_float(bhi), 0.0f) * w2hi;
        }
        S.spS[half][wih][m0] = s0;
        S.spS[half][wih][m1] = s1;
    }
    HBAR();

    // softmax (warp0)
    if (lt < 32) {
        float bias2 = S.cS[0];
        float v1 = S.spS[half][0][lt] + S.spS[half][1][lt] + bias2;
        v1 = (lt <= len) ? v1 : -INFINITY;
        float v2 = -INFINITY;
        if (lt + 32 < M_MEM) {
            v2 = S.spS[half][0][lt + 32] + S.spS[half][1][lt + 32] + bias2;
            v2 = (lt + 32 <= len) ? v2 : -INFINITY;
        }
        float mx = fmaxf(v1, v2);
        #pragma unroll
        for (int o = 16; o > 0; o >>= 1)
            mx = fmaxf(mx, __shfl_xor_sync(0xffffffffu, mx, o));
        float e1 = __expf(v1 - mx);
        float e2 = (lt + 32 < M_MEM) ? __expf(v2 - mx) : 0.0f;
        float sm = e1 + e2;
        #pragma unroll
        for (int o = 16; o > 0; o >>= 1)
            sm += __shfl_xor_sync(0xffffffffu, sm, o);
        float inv = __frcp_rn(sm);
        S.wtS[half][lt] = e1 * inv;
        if (lt + 32 < M_MEM) S.wtS[half][lt + 32] = e2 * inv;
    }
    HBAR();

    // weighted sum: both warps, lane = dim (warp0 d0-31, warp1 d32-63)
    {
        const int d = wih * 32 + l;
        float g = S.groupS[half][d];
        const float* mcol = S.memS[half] + d;
        const float4* wt4 = (const float4*)S.wtS[half];
        #pragma unroll 4
        for (int q = 0; q < 12; q++) {
            float4 w = wt4[q];
            g += w.x * mcol[(4 * q + 0) * PAD];
            g += w.y * mcol[(4 * q + 1) * PAD];
            g += w.z * mcol[(4 * q + 2) * PAD];
            g += w.w * mcol[(4 * q + 3) * PAD];
        }
        g += S.wtS[half][48] * mcol[48 * PAD];
        g += S.wtS[half][49] * mcol[49 * PAD];
        S.gS[half][d] = g;
    }
    HBAR();

    // pred MLP: 64 lanes, 8 k-phases; both warps publish partials, warp0 finishes
    {
        const int j = lt & 7;
        const int c = lt >> 3;          // 0..7
        float a = (c == 0) ? S.cS[1 + j] : 0.0f;
        #pragma unroll 8
        for (int kk = 0; kk < 24; kk++) {
            int k = c + 8 * kk;
            float v = (k < 64) ? S.gS[half][k] * S.itemS[half][k]
                   : (k < 128) ? S.gS[half][k - 64]
                               : S.itemS[half][k - 128];
            a += v * S.predW[k * 8 + j];
        }
        a += __shfl_xor_sync(0xffffffffu, a, 8);
        a += __shfl_xor_sync(0xffffffffu, a, 16);
        if (l < 8) S.spS[half][wih][l] = a;   // warp0 -> spS[.][0], warp1 -> spS[.][1]
    }
    HBAR();
    if (wih == 0 && l < 8) {
        const int j = l;
        float tot = S.spS[half][0][j] + S.spS[half][1][j];
        float part = fmaxf(tot, 0.0f) * S.cS[9 + j];
        part += __shfl_xor_sync(0x000000ffu, part, 1);
        part += __shfl_xor_sync(0x000000ffu, part, 2);
        part += __shfl_xor_sync(0x000000ffu, part, 4);
        if (l == 0 && valid) {
            float z = part + S.cS[17];
            out[b] = 1.0f / (1.0f + __expf(-z));
        }
    }
}

extern "C" void kernel_launch(void* const* d_in, const int* in_sizes, int n_in,
                              void* d_out, int out_size)
{
    const int*   group_inputs   = (const int*)  d_in[0];
    const int*   item_inputs    = (const int*)  d_in[1];
    const int*   member_ids     = (const int*)  d_in[2];
    const int*   member_lengths = (const int*)  d_in[3];
    const float* user_table     = (const float*)d_in[4];
    const float* item_table     = (const float*)d_in[5];
    const float* group_table    = (const float*)d_in[6];
    const float* att_w1         = (const float*)d_in[7];
    const float* att_b1         = (const float*)d_in[8];
    const float* att_w2         = (const float*)d_in[9];
    const float* att_b2         = (const float*)d_in[10];
    const float* pred_w1        = (const float*)d_in[11];
    const float* pred_b1        = (const float*)d_in[12];
    const float* pred_w2        = (const float*)d_in[13];
    const float* pred_b2        = (const float*)d_in[14];
    float* out = (float*)d_out;

    int B = in_sizes[0];
    int smemBytes = (int)sizeof(SmemLayout);
    cudaFuncSetAttribute(agree_fused_kernel2,
                         cudaFuncAttributeMaxDynamicSharedMemorySize, smemBytes);
    int grid = (B + HALVES - 1) / HALVES;
    agree_fused_kernel2<<<grid, 256, smemBytes>>>(
        group_inputs, item_inputs, member_ids, member_lengths,
        user_table, item_table, group_table,
        att_w1, att_b1, att_w2, att_b2,
        pred_w1, pred_b1, pred_w2, pred_b2, out, B);
}